// round 10
// baseline (speedup 1.0000x reference)
#include <cuda_runtime.h>
#include <math.h>

#define DD   2048
#define HH   8
#define KVH  2
#define HDIM 256
#define SS   4096
#define FFD  8192
#define PLD  256
#define LL   8
#define POSI 2048
#define EPSF 1e-6f
#define NSPL 65
#define CHNK 32   // 65*32 = 2080 >= 2049 positions

// ---------------- scratch (device globals; no allocation allowed) ----------------
__device__ float g_h[DD];
__device__ float g_hn[DD];
__device__ float g_qkv[HH*HDIM + 2*KVH*HDIM];   // 3072
__device__ float g_q[HH*HDIM];
__device__ float g_knew[KVH*HDIM];
__device__ float g_vnew[KVH*HDIM];
__device__ float g_attn[HH*HDIM];
__device__ float g_ff2[2*FFD];
__device__ float g_vec[DD];
__device__ float g_pl[PLD];
__device__ float g_part[HH * NSPL * (HDIM + 2)];
__device__ unsigned g_cnt[8];          // generic self-resetting tickets
__device__ unsigned g_cnt_attn[KVH];   // per-kv tickets

__device__ __forceinline__ float gelu_tanh(float x) {
    const float c = 0.7978845608028654f;
    return 0.5f * x * (1.0f + tanhf(c * (x + 0.044715f * x * x * x)));
}

__device__ __forceinline__ float warp_sum(float v) {
#pragma unroll
    for (int o = 16; o; o >>= 1) v += __shfl_xor_sync(0xffffffffu, v, o);
    return v;
}

__device__ __forceinline__ float warp_max(float v) {
#pragma unroll
    for (int o = 16; o; o >>= 1) v = fmaxf(v, __shfl_xor_sync(0xffffffffu, v, o));
    return v;
}

__device__ __forceinline__ float block_sum_512(float v, float* red) {
    int t = threadIdx.x;
    red[t] = v; __syncthreads();
    for (int s = 256; s > 0; s >>= 1) { if (t < s) red[t] += red[t + s]; __syncthreads(); }
    float r = red[0];
    __syncthreads();
    return r;
}

// store -> fence -> sync -> t0 atomic -> sync ; winner gets acquire fence
__device__ __forceinline__ bool last_block_ticket(unsigned* cnt, unsigned total) {
    __threadfence();
    __syncthreads();
    __shared__ unsigned isLast;
    if (threadIdx.x == 0) isLast = (atomicInc(cnt, total - 1) == total - 1);
    __syncthreads();
    if (!isLast) return false;
    __threadfence();
    return true;
}

// ---------------- KV cache bulk copy, SKIPPING row POSI of each plane ----------------
__global__ void __launch_bounds__(256) copy_kv_kernel(
        const float4* __restrict__ Ki, const float4* __restrict__ Vi,
        float4* __restrict__ Ko, float4* __restrict__ Vo, int n4) {
    int stride = gridDim.x * blockDim.x;
    for (int i = blockIdx.x * blockDim.x + threadIdx.x; i < n4; i += stride) {
        bool skip = (((i >> 6) & (SS - 1)) == POSI);   // 64 float4 per row
        if (!skip) {
            __stcs(&Ko[i], __ldcs(&Ki[i]));
            __stcs(&Vo[i], __ldcs(&Vi[i]));
        }
    }
}

// ---------------- h = hidden (copy) ; hn = rms(h) * w ----------------
__global__ void norm0_kernel(const float* __restrict__ hidden, const float* __restrict__ w,
                             float* __restrict__ h, float* __restrict__ hn) {
    __shared__ float red[256];
    int t = threadIdx.x;
    float hv[8]; float ss = 0.f;
#pragma unroll
    for (int j = 0; j < 8; j++) { hv[j] = hidden[t + j * 256]; ss += hv[j] * hv[j]; }
    red[t] = ss; __syncthreads();
    for (int s = 128; s > 0; s >>= 1) { if (t < s) red[t] += red[t + s]; __syncthreads(); }
    float r = rsqrtf(red[0] / (float)DD + EPSF);
#pragma unroll
    for (int j = 0; j < 8; j++) { int i = t + j * 256; h[i] = hv[j]; hn[i] = hv[j] * r * w[i]; }
}

// ---------------- fused QKV GEMV: 512 thr, warp-pair per row + last-block RMS/RoPE --------
__global__ void __launch_bounds__(512) gemv_qkv_kernel(
        const float* __restrict__ Wq, const float* __restrict__ Wk, const float* __restrict__ Wv,
        const float* __restrict__ x, float* __restrict__ y,
        const float* __restrict__ qn, const float* __restrict__ kn,
        const float* __restrict__ cosv, const float* __restrict__ sinv,
        float* __restrict__ q_out, float* __restrict__ knew, float* __restrict__ vnew,
        float* __restrict__ Kpos, float* __restrict__ Vpos,
        unsigned* __restrict__ cnt) {
    __shared__ float4 sx4[DD / 4];
    const float4* x4 = (const float4*)x;
    for (int i = threadIdx.x; i < DD / 4; i += 512) sx4[i] = x4[i];
    __syncthreads();
    int warp = threadIdx.x >> 5, lane = threadIdx.x & 31;
    int half = warp & 1;
    int row = blockIdx.x * 8 + (warp >> 1);
    const float* W; int r;
    if (row < 2048)      { W = Wq; r = row; }
    else if (row < 2560) { W = Wk; r = row - 2048; }
    else                 { W = Wv; r = row - 2560; }
    const int H4 = DD / 8;   // float4 per column-half
    const float4* Wr = (const float4*)(W + (size_t)r * DD) + half * H4;
    const float4* xs = sx4 + half * H4;
    float acc = 0.f;
#pragma unroll 8
    for (int i = lane; i < H4; i += 32) {
        float4 w = __ldcs(&Wr[i]); float4 v = xs[i];
        acc = fmaf(w.x, v.x, acc); acc = fmaf(w.y, v.y, acc);
        acc = fmaf(w.z, v.z, acc); acc = fmaf(w.w, v.w, acc);
    }
    acc = warp_sum(acc);
    __shared__ float sred[16];
    if (lane == 0) sred[warp] = acc;
    __syncthreads();
    if (threadIdx.x < 8)
        y[blockIdx.x * 8 + threadIdx.x] = sred[2 * threadIdx.x] + sred[2 * threadIdx.x + 1];

    if (!last_block_ticket(cnt, gridDim.x)) return;

    for (int u = warp; u < 12; u += 16) {
        const float* src; const float* nw = nullptr; int rope = 1;
        if (u < 8)        { src = y + u * HDIM; nw = qn; }
        else if (u < 10)  { src = y + HH * HDIM + (u - 8) * HDIM; nw = kn; }
        else              { src = y + HH * HDIM + KVH * HDIM + (u - 10) * HDIM; rope = 0; }
        float v8[8]; float ss = 0.f;
#pragma unroll
        for (int j = 0; j < 8; j++) { v8[j] = src[lane * 8 + j]; ss += v8[j] * v8[j]; }
        ss = warp_sum(ss);
        float rr = rsqrtf(ss / (float)HDIM + EPSF);
#pragma unroll
        for (int j = 0; j < 8; j++) {
            int d = lane * 8 + j;
            float val = v8[j] * rr;
            if (nw) val *= nw[d];
            if (rope) {
                int p = (d < 128) ? d + 128 : d - 128;
                float pv = src[p] * rr * (nw ? nw[p] : 1.f);
                float rot = (d < 128) ? -pv : pv;
                val = val * cosv[d] + rot * sinv[d];
            }
            if (u < 8)       q_out[u * HDIM + d] = val;
            else if (u < 10) {
                int kv = u - 8;
                knew[kv * HDIM + d] = val;
                Kpos[(size_t)kv * SS * HDIM + d] = val;
            } else {
                int kv = u - 10;
                vnew[kv * HDIM + d] = val;
                Vpos[(size_t)kv * SS * HDIM + d] = val;
            }
        }
    }
}

// ---------------- attention (unchanged): block = (kv, chunk of 32) ----------
__global__ void __launch_bounds__(256) attn_part_kernel(
        const float* __restrict__ q,
        const float* __restrict__ Kin, const float* __restrict__ Vin,
        const float* __restrict__ knew, const float* __restrict__ vnew,
        float* __restrict__ part, float* __restrict__ out) {
    int kv = blockIdx.x & 1;
    int chunk = blockIdx.x >> 1;
    const float* Kh = Kin + (size_t)kv * SS * HDIM;
    const float* Vh = Vin + (size_t)kv * SS * HDIM;
    const float* kn_ = knew + kv * HDIM;
    const float* vn_ = vnew + kv * HDIM;
    int t = threadIdx.x;
    int warp = t >> 5, lane = t & 31;
    int s0 = chunk * CHNK;
    int n = min(CHNK, POSI + 1 - s0);

    __shared__ float sq[4][HDIM];
    __shared__ float ssc[4][CHNK];
    __shared__ float sM[4], sL[4];
    __shared__ float spart[4][4][HDIM];
#pragma unroll
    for (int hh = 0; hh < 4; hh++) sq[hh][t] = q[(kv * 4 + hh) * HDIM + t];
    __syncthreads();

    float qreg[4][8];
#pragma unroll
    for (int hh = 0; hh < 4; hh++)
#pragma unroll
        for (int j = 0; j < 8; j++) qreg[hh][j] = sq[hh][lane * 8 + j];

    for (int idx = warp; idx < n; idx += 8) {
        int s = s0 + idx;
        const float* Kr = (s == POSI) ? kn_ : (Kh + (size_t)s * HDIM);
        float4 ka = *(const float4*)(Kr + lane * 8);
        float4 kb = *(const float4*)(Kr + lane * 8 + 4);
        float k8[8] = {ka.x, ka.y, ka.z, ka.w, kb.x, kb.y, kb.z, kb.w};
        float d0 = 0.f, d1 = 0.f, d2 = 0.f, d3 = 0.f;
#pragma unroll
        for (int j = 0; j < 8; j++) {
            d0 = fmaf(k8[j], qreg[0][j], d0);
            d1 = fmaf(k8[j], qreg[1][j], d1);
            d2 = fmaf(k8[j], qreg[2][j], d2);
            d3 = fmaf(k8[j], qreg[3][j], d3);
        }
        d0 = warp_sum(d0); d1 = warp_sum(d1);
        d2 = warp_sum(d2); d3 = warp_sum(d3);
        if (lane == 0) { ssc[0][idx] = d0; ssc[1][idx] = d1; ssc[2][idx] = d2; ssc[3][idx] = d3; }
    }
    __syncthreads();

    if (warp < 4) {
        float val = (lane < n) ? ssc[warp][lane] : -1e30f;
        float M = warp_max(val);
        float e = (lane < n) ? expf(val - M) : 0.f;
        float L = warp_sum(e);
        if (lane < n) ssc[warp][lane] = e;
        if (lane == 0) { sM[warp] = M; sL[warp] = L; }
    }
    __syncthreads();

    int g = t >> 6;
    int d4 = (t & 63);
    float acc[4][4];
#pragma unroll
    for (int u = 0; u < 4; u++)
#pragma unroll
        for (int j = 0; j < 4; j++) acc[u][j] = 0.f;
#pragma unroll 2
    for (int idx = g; idx < n; idx += 4) {
        int s = s0 + idx;
        const float4* Vr4 = (const float4*)((s == POSI) ? vn_ : (Vh + (size_t)s * HDIM));
        float4 v = Vr4[d4];
#pragma unroll
        for (int u = 0; u < 4; u++) {
            float p = ssc[u][idx];
            acc[u][0] = fmaf(p, v.x, acc[u][0]);
            acc[u][1] = fmaf(p, v.y, acc[u][1]);
            acc[u][2] = fmaf(p, v.z, acc[u][2]);
            acc[u][3] = fmaf(p, v.w, acc[u][3]);
        }
    }
#pragma unroll
    for (int u = 0; u < 4; u++)
        *(float4*)&spart[g][u][d4 * 4] = make_float4(acc[u][0], acc[u][1], acc[u][2], acc[u][3]);
    __syncthreads();

#pragma unroll
    for (int u = 0; u < 4; u++) {
        float num = spart[0][u][t] + spart[1][u][t] + spart[2][u][t] + spart[3][u][t];
        float* pp = part + (size_t)((kv * 4 + u) * NSPL + chunk) * (HDIM + 2);
        pp[t] = num;
        if (t == 0) { pp[HDIM] = sM[u]; pp[HDIM + 1] = sL[u]; }
    }

    if (!last_block_ticket(&g_cnt_attn[kv], NSPL)) return;
    __shared__ float cf[4][NSPL];
    __shared__ float cLg[4];
    if (t < 4) {
        float Mg = -1e30f;
        for (int c = 0; c < NSPL; c++)
            Mg = fmaxf(Mg, part[(size_t)((kv * 4 + t) * NSPL + c) * (HDIM + 2) + HDIM]);
        float Lg = 0.f;
        for (int c = 0; c < NSPL; c++) {
            const float* pp = part + (size_t)((kv * 4 + t) * NSPL + c) * (HDIM + 2);
            float f = expf(pp[HDIM] - Mg);
            Lg += pp[HDIM + 1] * f;
            cf[t][c] = f;
        }
        cLg[t] = Lg;
    }
    __syncthreads();
#pragma unroll
    for (int u = 0; u < 4; u++) {
        float num = 0.f;
        for (int c = 0; c < NSPL; c++)
            num = fmaf(part[(size_t)((kv * 4 + u) * NSPL + c) * (HDIM + 2) + t], cf[u][c], num);
        out[(kv * 4 + u) * HDIM + t] = num / cLg[u];
    }
}

// ---------------- dual-matrix GEMV for Wg/Wu: 512 thr, warp per row, 16 rows/block ----------
__global__ void __launch_bounds__(512) gemv_wgwu_kernel(
        const float* __restrict__ Wg, const float* __restrict__ Wu,
        const float* __restrict__ x, float* __restrict__ y) {
    __shared__ float4 sx4[DD / 4];
    const float4* x4 = (const float4*)x;
    for (int i = threadIdx.x; i < DD / 4; i += 512) sx4[i] = x4[i];
    __syncthreads();
    int lane = threadIdx.x & 31;
    int row = blockIdx.x * 16 + (threadIdx.x >> 5);
    const float* W; int r;
    if (row < FFD) { W = Wg; r = row; } else { W = Wu; r = row - FFD; }
    const float4* Wr = (const float4*)(W + (size_t)r * DD);
    float acc = 0.f;
#pragma unroll 8
    for (int i = lane; i < DD / 4; i += 32) {
        float4 w = __ldcs(&Wr[i]); float4 v = sx4[i];
        acc = fmaf(w.x, v.x, acc); acc = fmaf(w.y, v.y, acc);
        acc = fmaf(w.z, v.z, acc); acc = fmaf(w.w, v.w, acc);
    }
    acc = warp_sum(acc);
    if (lane == 0) y[row] = acc;
}

// ---------------- generic 512-thr GEMV, warp-pair per row, 8 rows/block -----------------
// GATE: x has 2*COLS elements; staged x[i] = gelu(x[i]) * x[i+COLS]
// MODE 0: y = Wx ; MODE 1: y = gelu(Wx)*aux
// MODE 2: + last block: h += rms(y)*w1 ; if (w2) hn = rms(h)*w2
// MODE 3: + last block: h = (h + rms(y)*w1)*sc ; if (w2) hn = rms(h)*w2 ; if (out2) out2 = h
template<int COLS, int MODE, int GATE>
__global__ void __launch_bounds__(512) gemv_kernel(
        const float* __restrict__ W, const float* __restrict__ x, float* __restrict__ y,
        const float* __restrict__ aux,
        const float* __restrict__ w1, float* __restrict__ h,
        const float* __restrict__ w2, float* __restrict__ hn,
        const float* __restrict__ scp, float* __restrict__ out2,
        unsigned* __restrict__ cnt) {
    __shared__ float4 sx4[COLS / 4];
    const float4* x4 = (const float4*)x;
    for (int i = threadIdx.x; i < COLS / 4; i += 512) {
        if (GATE) {
            float4 gg = x4[i];
            float4 uu = x4[i + COLS / 4];
            sx4[i] = make_float4(gelu_tanh(gg.x) * uu.x, gelu_tanh(gg.y) * uu.y,
                                 gelu_tanh(gg.z) * uu.z, gelu_tanh(gg.w) * uu.w);
        } else {
            sx4[i] = x4[i];
        }
    }
    __syncthreads();
    int warp = threadIdx.x >> 5, lane = threadIdx.x & 31;
    int half = warp & 1;
    int row = blockIdx.x * 8 + (warp >> 1);
    const int H4 = COLS / 8;
    const float4* Wr = (const float4*)(W + (size_t)row * COLS) + half * H4;
    const float4* xs = sx4 + half * H4;
    float acc = 0.f;
#pragma unroll 8
    for (int i = lane; i < H4; i += 32) {
        float4 w = __ldcs(&Wr[i]); float4 v = xs[i];
        acc = fmaf(w.x, v.x, acc); acc = fmaf(w.y, v.y, acc);
        acc = fmaf(w.z, v.z, acc); acc = fmaf(w.w, v.w, acc);
    }
    acc = warp_sum(acc);
    __shared__ float sred[16];
    if (lane == 0) sred[warp] = acc;
    __syncthreads();
    if (threadIdx.x < 8) {
        float r = sred[2 * threadIdx.x] + sred[2 * threadIdx.x + 1];
        int rr = blockIdx.x * 8 + threadIdx.x;
        if (MODE == 1) r = gelu_tanh(r) * aux[rr];
        y[rr] = r;
    }
    if (MODE < 2) return;

    if (!last_block_ticket(cnt, gridDim.x)) return;

    __shared__ float red[512];
    int t = threadIdx.x;
    float vv[4], hv[4]; float ss = 0.f;
#pragma unroll
    for (int j = 0; j < 4; j++) { int i = t + j * 512; vv[j] = y[i]; ss += vv[j] * vv[j]; }
    ss = block_sum_512(ss, red);
    float r1 = rsqrtf(ss / (float)DD + EPSF);
    float sc = (MODE == 3) ? scp[0] : 1.f;
    float ss2 = 0.f;
#pragma unroll
    for (int j = 0; j < 4; j++) {
        int i = t + j * 512;
        float nh = h[i] + vv[j] * r1 * w1[i];
        if (MODE == 3) nh *= sc;
        hv[j] = nh;
        h[i] = nh;
        if (MODE == 3 && out2) out2[i] = nh;
        ss2 += nh * nh;
    }
    if (w2) {
        ss2 = block_sum_512(ss2, red);
        float r2 = rsqrtf(ss2 / (float)DD + EPSF);
#pragma unroll
        for (int j = 0; j < 4; j++) { int i = t + j * 512; hn[i] = hv[j] * r2 * w2[i]; }
    }
}

// ==================================================================================
extern "C" void kernel_launch(void* const* d_in, const int* in_sizes, int n_in,
                              void* d_out, int out_size) {
    const float* hidden = (const float*)d_in[0];
    const float* pls    = (const float*)d_in[3];
    const float* cos_s  = (const float*)d_in[4];
    const float* sin_s  = (const float*)d_in[5];
    const float* cos_f  = (const float*)d_in[6];
    const float* sin_f  = (const float*)d_in[7];
    const float* K_in   = (const float*)d_in[8];
    const float* V_in   = (const float*)d_in[9];
    const float* Wq     = (const float*)d_in[10];
    const float* Wk     = (const float*)d_in[11];
    const float* Wv     = (const float*)d_in[12];
    const float* Wo     = (const float*)d_in[13];
    const float* qn     = (const float*)d_in[14];
    const float* kn     = (const float*)d_in[15];
    const float* ln_in  = (const float*)d_in[16];
    const float* ln_pa  = (const float*)d_in[17];
    const float* ln_pre = (const float*)d_in[18];
    const float* ln_post= (const float*)d_in[19];
    const float* ln_pl  = (const float*)d_in[20];
    const float* Wg     = (const float*)d_in[21];
    const float* Wu     = (const float*)d_in[22];
    const float* Wd     = (const float*)d_in[23];
    const float* Wplg   = (const float*)d_in[24];
    const float* Wplp   = (const float*)d_in[25];
    const float* lsc    = (const float*)d_in[26];

    float* out  = (float*)d_out;
    float* outK = out + DD;
    float* outV = outK + (size_t)LL * KVH * SS * HDIM;

    float *h_, *hn_, *qkv_, *q_, *knew_, *vnew_, *attn_, *ff2_, *vec_, *pl_, *part_;
    unsigned* cnt_;
    cudaGetSymbolAddress((void**)&h_,    g_h);
    cudaGetSymbolAddress((void**)&hn_,   g_hn);
    cudaGetSymbolAddress((void**)&qkv_,  g_qkv);
    cudaGetSymbolAddress((void**)&q_,    g_q);
    cudaGetSymbolAddress((void**)&knew_, g_knew);
    cudaGetSymbolAddress((void**)&vnew_, g_vnew);
    cudaGetSymbolAddress((void**)&attn_, g_attn);
    cudaGetSymbolAddress((void**)&ff2_,  g_ff2);
    cudaGetSymbolAddress((void**)&vec_,  g_vec);
    cudaGetSymbolAddress((void**)&pl_,   g_pl);
    cudaGetSymbolAddress((void**)&part_, g_part);
    cudaGetSymbolAddress((void**)&cnt_,  g_cnt);

    static cudaStream_t side = nullptr;
    static cudaEvent_t evFork = nullptr, evJoin = nullptr;
    if (!side) {
        int loPri = 0, hiPri = 0;
        cudaDeviceGetStreamPriorityRange(&loPri, &hiPri);
        cudaStreamCreateWithPriority(&side, cudaStreamNonBlocking, loPri);  // lowest priority
        cudaEventCreateWithFlags(&evFork, cudaEventDisableTiming);
        cudaEventCreateWithFlags(&evJoin, cudaEventDisableTiming);
    }

    // fork: KV bulk copy overlaps the entire layer loop (low priority, 1 block/SM footprint)
    cudaEventRecord(evFork, 0);
    cudaStreamWaitEvent(side, evFork, 0);
    const int kvN4 = LL * KVH * SS * HDIM / 4;
    copy_kv_kernel<<<1184, 256, 0, side>>>((const float4*)K_in, (const float4*)V_in,
                                           (float4*)outK, (float4*)outV, kvN4);
    cudaEventRecord(evJoin, side);

    norm0_kernel<<<1, 256>>>(hidden, ln_in, h_, hn_);

    for (int l = 0; l < LL; l++) {
        const float* cosp = (l == 4) ? cos_f : cos_s;   // is_full only layer 4 (L=8)
        const float* sinp = (l == 4) ? sin_f : sin_s;

        const float* Wq_l   = Wq   + (size_t)l * HH * HDIM * DD;
        const float* Wk_l   = Wk   + (size_t)l * KVH * HDIM * DD;
        const float* Wv_l   = Wv   + (size_t)l * KVH * HDIM * DD;
        const float* Wo_l   = Wo   + (size_t)l * DD * HH * HDIM;
        const float* Wg_l   = Wg   + (size_t)l * FFD * DD;
        const float* Wu_l   = Wu   + (size_t)l * FFD * DD;
        const float* Wd_l   = Wd   + (size_t)l * DD * FFD;
        const float* Wplg_l = Wplg + (size_t)l * PLD * DD;
        const float* Wplp_l = Wplp + (size_t)l * DD * PLD;

        const float* Kin_l = K_in + (size_t)l * KVH * SS * HDIM;
        const float* Vin_l = V_in + (size_t)l * KVH * SS * HDIM;
        float* Kpos = outK + (size_t)l * KVH * SS * HDIM + (size_t)POSI * HDIM;
        float* Vpos = outV + (size_t)l * KVH * SS * HDIM + (size_t)POSI * HDIM;

        // attention block
        gemv_qkv_kernel<<<384, 512>>>(Wq_l, Wk_l, Wv_l, hn_, qkv_,
                                      qn + l * HDIM, kn + l * HDIM, cosp, sinp,
                                      q_, knew_, vnew_, Kpos, Vpos, cnt_ + 0);
        attn_part_kernel<<<KVH * NSPL, 256>>>(q_, Kin_l, Vin_l, knew_, vnew_, part_, attn_);
        gemv_kernel<DD, 2, 0><<<256, 512>>>(Wo_l, attn_, vec_, nullptr,
                                            ln_pa + l * DD, h_, ln_pre + l * DD, hn_,
                                            nullptr, nullptr, cnt_ + 1);
        // MLP block
        gemv_wgwu_kernel<<<1024, 512>>>(Wg_l, Wu_l, hn_, ff2_);
        gemv_kernel<FFD, 2, 1><<<256, 512>>>(Wd_l, ff2_, vec_, nullptr,
                                             ln_post + l * DD, h_, nullptr, nullptr,
                                             nullptr, nullptr, cnt_ + 2);
        // per-layer embedding block (uses h directly)
        gemv_kernel<DD, 1, 0><<<32, 512>>>(Wplg_l, h_, pl_, pls + l * PLD,
                                           nullptr, nullptr, nullptr, nullptr,
                                           nullptr, nullptr, nullptr);
        gemv_kernel<PLD, 3, 0><<<256, 512>>>(Wplp_l, pl_, vec_, nullptr,
                                             ln_pl + l * DD, h_,
                                             (l < LL - 1) ? (ln_in + (l + 1) * DD) : nullptr, hn_,
                                             lsc + l, (l == LL - 1) ? out : nullptr, cnt_ + 3);
    }

    cudaStreamWaitEvent(0, evJoin, 0);
}

// round 11
// speedup vs baseline: 1.0390x; 1.0390x over previous
#include <cuda_runtime.h>
#include <math.h>

#define DD   2048
#define HH   8
#define KVH  2
#define HDIM 256
#define SS   4096
#define FFD  8192
#define PLD  256
#define LL   8
#define POSI 2048
#define EPSF 1e-6f
#define NSPL 129
#define CHNK 16   // 129*16 = 2064 >= 2049 positions

// ---------------- scratch (device globals; no allocation allowed) ----------------
__device__ float g_h[DD];
__device__ float g_hn[DD];
__device__ float g_qkv[HH*HDIM + 2*KVH*HDIM];   // 3072
__device__ float g_q[HH*HDIM];
__device__ float g_knew[KVH*HDIM];
__device__ float g_vnew[KVH*HDIM];
__device__ float g_attn[HH*HDIM];
__device__ float g_ff2[2*FFD];
__device__ float g_vec[DD];
__device__ float g_pl[PLD];
__device__ float g_part[HH * NSPL * (HDIM + 2)];
__device__ unsigned g_cnt[8];          // generic self-resetting tickets

__device__ __forceinline__ float gelu_tanh(float x) {
    const float c = 0.7978845608028654f;
    return 0.5f * x * (1.0f + tanhf(c * (x + 0.044715f * x * x * x)));
}

__device__ __forceinline__ float warp_sum(float v) {
#pragma unroll
    for (int o = 16; o; o >>= 1) v += __shfl_xor_sync(0xffffffffu, v, o);
    return v;
}

__device__ __forceinline__ float warp_max(float v) {
#pragma unroll
    for (int o = 16; o; o >>= 1) v = fmaxf(v, __shfl_xor_sync(0xffffffffu, v, o));
    return v;
}

__device__ __forceinline__ float block_sum_512(float v, float* red) {
    int t = threadIdx.x;
    red[t] = v; __syncthreads();
    for (int s = 256; s > 0; s >>= 1) { if (t < s) red[t] += red[t + s]; __syncthreads(); }
    float r = red[0];
    __syncthreads();
    return r;
}

// store -> fence -> sync -> t0 atomic -> sync ; winner gets acquire fence
__device__ __forceinline__ bool last_block_ticket(unsigned* cnt, unsigned total) {
    __threadfence();
    __syncthreads();
    __shared__ unsigned isLast;
    if (threadIdx.x == 0) isLast = (atomicInc(cnt, total - 1) == total - 1);
    __syncthreads();
    if (!isLast) return false;
    __threadfence();
    return true;
}

// ---------------- KV cache bulk copy, SKIPPING row POSI of each plane ----------------
__global__ void __launch_bounds__(256) copy_kv_kernel(
        const float4* __restrict__ Ki, const float4* __restrict__ Vi,
        float4* __restrict__ Ko, float4* __restrict__ Vo, int n4) {
    int stride = gridDim.x * blockDim.x;
    for (int i = blockIdx.x * blockDim.x + threadIdx.x; i < n4; i += stride) {
        bool skip = (((i >> 6) & (SS - 1)) == POSI);   // 64 float4 per row
        if (!skip) {
            Ko[i] = Ki[i];
            Vo[i] = Vi[i];
        }
    }
}

// ---------------- h = hidden (copy) ; hn = rms(h) * w ----------------
__global__ void norm0_kernel(const float* __restrict__ hidden, const float* __restrict__ w,
                             float* __restrict__ h, float* __restrict__ hn) {
    __shared__ float red[256];
    int t = threadIdx.x;
    float hv[8]; float ss = 0.f;
#pragma unroll
    for (int j = 0; j < 8; j++) { hv[j] = hidden[t + j * 256]; ss += hv[j] * hv[j]; }
    red[t] = ss; __syncthreads();
    for (int s = 128; s > 0; s >>= 1) { if (t < s) red[t] += red[t + s]; __syncthreads(); }
    float r = rsqrtf(red[0] / (float)DD + EPSF);
#pragma unroll
    for (int j = 0; j < 8; j++) { int i = t + j * 256; h[i] = hv[j]; hn[i] = hv[j] * r * w[i]; }
}

// ---------------- fused QKV GEMV: 512 thr, warp-pair per row + last-block RMS/RoPE --------
__global__ void __launch_bounds__(512) gemv_qkv_kernel(
        const float* __restrict__ Wq, const float* __restrict__ Wk, const float* __restrict__ Wv,
        const float* __restrict__ x, float* __restrict__ y,
        const float* __restrict__ qn, const float* __restrict__ kn,
        const float* __restrict__ cosv, const float* __restrict__ sinv,
        float* __restrict__ q_out, float* __restrict__ knew, float* __restrict__ vnew,
        float* __restrict__ Kpos, float* __restrict__ Vpos,
        unsigned* __restrict__ cnt) {
    __shared__ float4 sx4[DD / 4];
    const float4* x4 = (const float4*)x;
    for (int i = threadIdx.x; i < DD / 4; i += 512) sx4[i] = x4[i];
    __syncthreads();
    int warp = threadIdx.x >> 5, lane = threadIdx.x & 31;
    int half = warp & 1;
    int row = blockIdx.x * 8 + (warp >> 1);
    const float* W; int r;
    if (row < 2048)      { W = Wq; r = row; }
    else if (row < 2560) { W = Wk; r = row - 2048; }
    else                 { W = Wv; r = row - 2560; }
    const int H4 = DD / 8;   // float4 per column-half
    const float4* Wr = (const float4*)(W + (size_t)r * DD) + half * H4;
    const float4* xs = sx4 + half * H4;
    float acc = 0.f;
#pragma unroll 8
    for (int i = lane; i < H4; i += 32) {
        float4 w = Wr[i]; float4 v = xs[i];
        acc = fmaf(w.x, v.x, acc); acc = fmaf(w.y, v.y, acc);
        acc = fmaf(w.z, v.z, acc); acc = fmaf(w.w, v.w, acc);
    }
    acc = warp_sum(acc);
    __shared__ float sred[16];
    if (lane == 0) sred[warp] = acc;
    __syncthreads();
    if (threadIdx.x < 8)
        y[blockIdx.x * 8 + threadIdx.x] = sred[2 * threadIdx.x] + sred[2 * threadIdx.x + 1];

    if (!last_block_ticket(cnt, gridDim.x)) return;

    for (int u = warp; u < 12; u += 16) {
        const float* src; const float* nw = nullptr; int rope = 1;
        if (u < 8)        { src = y + u * HDIM; nw = qn; }
        else if (u < 10)  { src = y + HH * HDIM + (u - 8) * HDIM; nw = kn; }
        else              { src = y + HH * HDIM + KVH * HDIM + (u - 10) * HDIM; rope = 0; }
        float v8[8]; float ss = 0.f;
#pragma unroll
        for (int j = 0; j < 8; j++) { v8[j] = src[lane * 8 + j]; ss += v8[j] * v8[j]; }
        ss = warp_sum(ss);
        float rr = rsqrtf(ss / (float)HDIM + EPSF);
#pragma unroll
        for (int j = 0; j < 8; j++) {
            int d = lane * 8 + j;
            float val = v8[j] * rr;
            if (nw) val *= nw[d];
            if (rope) {
                int p = (d < 128) ? d + 128 : d - 128;
                float pv = src[p] * rr * (nw ? nw[p] : 1.f);
                float rot = (d < 128) ? -pv : pv;
                val = val * cosv[d] + rot * sinv[d];
            }
            if (u < 8)       q_out[u * HDIM + d] = val;
            else if (u < 10) {
                int kv = u - 8;
                knew[kv * HDIM + d] = val;
                Kpos[(size_t)kv * SS * HDIM + d] = val;
            } else {
                int kv = u - 10;
                vnew[kv * HDIM + d] = val;
                Vpos[(size_t)kv * SS * HDIM + d] = val;
            }
        }
    }
}

// ---------------- attention partials: block = (kv, chunk of 16); NO ticket, NO tail --------
__global__ void __launch_bounds__(256) attn_part_kernel(
        const float* __restrict__ q,
        const float* __restrict__ Kin, const float* __restrict__ Vin,
        const float* __restrict__ knew, const float* __restrict__ vnew,
        float* __restrict__ part) {
    int kv = blockIdx.x & 1;
    int chunk = blockIdx.x >> 1;
    const float* Kh = Kin + (size_t)kv * SS * HDIM;
    const float* Vh = Vin + (size_t)kv * SS * HDIM;
    const float* kn_ = knew + kv * HDIM;
    const float* vn_ = vnew + kv * HDIM;
    int t = threadIdx.x;
    int warp = t >> 5, lane = t & 31;
    int s0 = chunk * CHNK;
    int n = min(CHNK, POSI + 1 - s0);

    __shared__ float sq[4][HDIM];
    __shared__ float ssc[4][CHNK];
    __shared__ float sM[4], sL[4];
    __shared__ float spart[4][4][HDIM];
#pragma unroll
    for (int hh = 0; hh < 4; hh++) sq[hh][t] = q[(kv * 4 + hh) * HDIM + t];
    __syncthreads();

    float qreg[4][8];
#pragma unroll
    for (int hh = 0; hh < 4; hh++)
#pragma unroll
        for (int j = 0; j < 8; j++) qreg[hh][j] = sq[hh][lane * 8 + j];

    // Phase A: scores, warp per position (max 2 iterations), 4 heads per K read
    for (int idx = warp; idx < n; idx += 8) {
        int s = s0 + idx;
        const float* Kr = (s == POSI) ? kn_ : (Kh + (size_t)s * HDIM);
        float4 ka = *(const float4*)(Kr + lane * 8);
        float4 kb = *(const float4*)(Kr + lane * 8 + 4);
        float k8[8] = {ka.x, ka.y, ka.z, ka.w, kb.x, kb.y, kb.z, kb.w};
        float d0 = 0.f, d1 = 0.f, d2 = 0.f, d3 = 0.f;
#pragma unroll
        for (int j = 0; j < 8; j++) {
            d0 = fmaf(k8[j], qreg[0][j], d0);
            d1 = fmaf(k8[j], qreg[1][j], d1);
            d2 = fmaf(k8[j], qreg[2][j], d2);
            d3 = fmaf(k8[j], qreg[3][j], d3);
        }
        d0 = warp_sum(d0); d1 = warp_sum(d1);
        d2 = warp_sum(d2); d3 = warp_sum(d3);
        if (lane == 0) { ssc[0][idx] = d0; ssc[1][idx] = d1; ssc[2][idx] = d2; ssc[3][idx] = d3; }
    }
    __syncthreads();

    // Phase B: per-head softmax over <=16 positions (warp per head)
    if (warp < 4) {
        float val = (lane < n) ? ssc[warp][lane] : -1e30f;
        float M = warp_max(val);
        float e = (lane < n) ? expf(val - M) : 0.f;
        float L = warp_sum(e);
        if (lane < n) ssc[warp][lane] = e;
        if (lane == 0) { sM[warp] = M; sL[warp] = L; }
    }
    __syncthreads();

    // Phase C: V accumulation; 4 position-groups in parallel, float4 V loads
    int g = t >> 6;
    int d4 = (t & 63);
    float acc[4][4];
#pragma unroll
    for (int u = 0; u < 4; u++)
#pragma unroll
        for (int j = 0; j < 4; j++) acc[u][j] = 0.f;
    for (int idx = g; idx < n; idx += 4) {
        int s = s0 + idx;
        const float4* Vr4 = (const float4*)((s == POSI) ? vn_ : (Vh + (size_t)s * HDIM));
        float4 v = Vr4[d4];
#pragma unroll
        for (int u = 0; u < 4; u++) {
            float p = ssc[u][idx];
            acc[u][0] = fmaf(p, v.x, acc[u][0]);
            acc[u][1] = fmaf(p, v.y, acc[u][1]);
            acc[u][2] = fmaf(p, v.z, acc[u][2]);
            acc[u][3] = fmaf(p, v.w, acc[u][3]);
        }
    }
#pragma unroll
    for (int u = 0; u < 4; u++)
        *(float4*)&spart[g][u][d4 * 4] = make_float4(acc[u][0], acc[u][1], acc[u][2], acc[u][3]);
    __syncthreads();

#pragma unroll
    for (int u = 0; u < 4; u++) {
        float num = spart[0][u][t] + spart[1][u][t] + spart[2][u][t] + spart[3][u][t];
        float* pp = part + (size_t)((kv * 4 + u) * NSPL + chunk) * (HDIM + 2);
        pp[t] = num;
        if (t == 0) { pp[HDIM] = sM[u]; pp[HDIM + 1] = sL[u]; }
    }
}

// ---------------- attention combine: 8 blocks (one per head), fully parallel --------
__global__ void __launch_bounds__(256) attn_comb_kernel(
        const float* __restrict__ part, float* __restrict__ out) {
    int hh = blockIdx.x;
    int t = threadIdx.x;
    __shared__ float red[256];
    __shared__ float cf[NSPL];
    const float* base = part + (size_t)hh * NSPL * (HDIM + 2);

    float m = (t < NSPL) ? base[(size_t)t * (HDIM + 2) + HDIM] : -1e30f;
    red[t] = m; __syncthreads();
    for (int s = 128; s > 0; s >>= 1) { if (t < s) red[t] = fmaxf(red[t], red[t + s]); __syncthreads(); }
    float Mg = red[0];
    __syncthreads();
    float f = (t < NSPL) ? expf(m - Mg) : 0.f;
    float lv = (t < NSPL) ? base[(size_t)t * (HDIM + 2) + HDIM + 1] * f : 0.f;
    if (t < NSPL) cf[t] = f;
    red[t] = lv; __syncthreads();
    for (int s = 128; s > 0; s >>= 1) { if (t < s) red[t] += red[t + s]; __syncthreads(); }
    float Lg = red[0];
    __syncthreads();

    float num = 0.f;
#pragma unroll 8
    for (int c = 0; c < NSPL; c++)
        num = fmaf(base[(size_t)c * (HDIM + 2) + t], cf[c], num);
    out[hh * HDIM + t] = num / Lg;
}

// ---------------- dual-matrix GEMV for Wg/Wu: 512 thr, warp per row, 16 rows/block ----------
__global__ void __launch_bounds__(512) gemv_wgwu_kernel(
        const float* __restrict__ Wg, const float* __restrict__ Wu,
        const float* __restrict__ x, float* __restrict__ y) {
    __shared__ float4 sx4[DD / 4];
    const float4* x4 = (const float4*)x;
    for (int i = threadIdx.x; i < DD / 4; i += 512) sx4[i] = x4[i];
    __syncthreads();
    int lane = threadIdx.x & 31;
    int row = blockIdx.x * 16 + (threadIdx.x >> 5);
    const float* W; int r;
    if (row < FFD) { W = Wg; r = row; } else { W = Wu; r = row - FFD; }
    const float4* Wr = (const float4*)(W + (size_t)r * DD);
    float acc = 0.f;
#pragma unroll 8
    for (int i = lane; i < DD / 4; i += 32) {
        float4 w = Wr[i]; float4 v = sx4[i];
        acc = fmaf(w.x, v.x, acc); acc = fmaf(w.y, v.y, acc);
        acc = fmaf(w.z, v.z, acc); acc = fmaf(w.w, v.w, acc);
    }
    acc = warp_sum(acc);
    if (lane == 0) y[row] = acc;
}

// ---------------- generic 512-thr GEMV, warp-pair per row, 8 rows/block -----------------
// GATE: x has 2*COLS elements; staged x[i] = gelu(x[i]) * x[i+COLS]
// MODE 0: y = Wx ; MODE 1: y = gelu(Wx)*aux
// MODE 2: + last block: h += rms(y)*w1 ; if (w2) hn = rms(h)*w2
// MODE 3: + last block: h = (h + rms(y)*w1)*sc ; if (w2) hn = rms(h)*w2 ; if (out2) out2 = h
template<int COLS, int MODE, int GATE>
__global__ void __launch_bounds__(512) gemv_kernel(
        const float* __restrict__ W, const float* __restrict__ x, float* __restrict__ y,
        const float* __restrict__ aux,
        const float* __restrict__ w1, float* __restrict__ h,
        const float* __restrict__ w2, float* __restrict__ hn,
        const float* __restrict__ scp, float* __restrict__ out2,
        unsigned* __restrict__ cnt) {
    __shared__ float4 sx4[COLS / 4];
    const float4* x4 = (const float4*)x;
    for (int i = threadIdx.x; i < COLS / 4; i += 512) {
        if (GATE) {
            float4 gg = x4[i];
            float4 uu = x4[i + COLS / 4];
            sx4[i] = make_float4(gelu_tanh(gg.x) * uu.x, gelu_tanh(gg.y) * uu.y,
                                 gelu_tanh(gg.z) * uu.z, gelu_tanh(gg.w) * uu.w);
        } else {
            sx4[i] = x4[i];
        }
    }
    __syncthreads();
    int warp = threadIdx.x >> 5, lane = threadIdx.x & 31;
    int half = warp & 1;
    int row = blockIdx.x * 8 + (warp >> 1);
    const int H4 = COLS / 8;
    const float4* Wr = (const float4*)(W + (size_t)row * COLS) + half * H4;
    const float4* xs = sx4 + half * H4;
    float acc = 0.f;
#pragma unroll 8
    for (int i = lane; i < H4; i += 32) {
        float4 w = Wr[i]; float4 v = xs[i];
        acc = fmaf(w.x, v.x, acc); acc = fmaf(w.y, v.y, acc);
        acc = fmaf(w.z, v.z, acc); acc = fmaf(w.w, v.w, acc);
    }
    acc = warp_sum(acc);
    __shared__ float sred[16];
    if (lane == 0) sred[warp] = acc;
    __syncthreads();
    if (threadIdx.x < 8) {
        float r = sred[2 * threadIdx.x] + sred[2 * threadIdx.x + 1];
        int rr = blockIdx.x * 8 + threadIdx.x;
        if (MODE == 1) r = gelu_tanh(r) * aux[rr];
        y[rr] = r;
    }
    if (MODE < 2) return;

    if (!last_block_ticket(cnt, gridDim.x)) return;

    __shared__ float red[512];
    int t = threadIdx.x;
    float vv[4], hv[4]; float ss = 0.f;
#pragma unroll
    for (int j = 0; j < 4; j++) { int i = t + j * 512; vv[j] = y[i]; ss += vv[j] * vv[j]; }
    ss = block_sum_512(ss, red);
    float r1 = rsqrtf(ss / (float)DD + EPSF);
    float sc = (MODE == 3) ? scp[0] : 1.f;
    float ss2 = 0.f;
#pragma unroll
    for (int j = 0; j < 4; j++) {
        int i = t + j * 512;
        float nh = h[i] + vv[j] * r1 * w1[i];
        if (MODE == 3) nh *= sc;
        hv[j] = nh;
        h[i] = nh;
        if (MODE == 3 && out2) out2[i] = nh;
        ss2 += nh * nh;
    }
    if (w2) {
        ss2 = block_sum_512(ss2, red);
        float r2 = rsqrtf(ss2 / (float)DD + EPSF);
#pragma unroll
        for (int j = 0; j < 4; j++) { int i = t + j * 512; hn[i] = hv[j] * r2 * w2[i]; }
    }
}

// ==================================================================================
extern "C" void kernel_launch(void* const* d_in, const int* in_sizes, int n_in,
                              void* d_out, int out_size) {
    const float* hidden = (const float*)d_in[0];
    const float* pls    = (const float*)d_in[3];
    const float* cos_s  = (const float*)d_in[4];
    const float* sin_s  = (const float*)d_in[5];
    const float* cos_f  = (const float*)d_in[6];
    const float* sin_f  = (const float*)d_in[7];
    const float* K_in   = (const float*)d_in[8];
    const float* V_in   = (const float*)d_in[9];
    const float* Wq     = (const float*)d_in[10];
    const float* Wk     = (const float*)d_in[11];
    const float* Wv     = (const float*)d_in[12];
    const float* Wo     = (const float*)d_in[13];
    const float* qn     = (const float*)d_in[14];
    const float* kn     = (const float*)d_in[15];
    const float* ln_in  = (const float*)d_in[16];
    const float* ln_pa  = (const float*)d_in[17];
    const float* ln_pre = (const float*)d_in[18];
    const float* ln_post= (const float*)d_in[19];
    const float* ln_pl  = (const float*)d_in[20];
    const float* Wg     = (const float*)d_in[21];
    const float* Wu     = (const float*)d_in[22];
    const float* Wd     = (const float*)d_in[23];
    const float* Wplg   = (const float*)d_in[24];
    const float* Wplp   = (const float*)d_in[25];
    const float* lsc    = (const float*)d_in[26];

    float* out  = (float*)d_out;
    float* outK = out + DD;
    float* outV = outK + (size_t)LL * KVH * SS * HDIM;

    float *h_, *hn_, *qkv_, *q_, *knew_, *vnew_, *attn_, *ff2_, *vec_, *pl_, *part_;
    unsigned* cnt_;
    cudaGetSymbolAddress((void**)&h_,    g_h);
    cudaGetSymbolAddress((void**)&hn_,   g_hn);
    cudaGetSymbolAddress((void**)&qkv_,  g_qkv);
    cudaGetSymbolAddress((void**)&q_,    g_q);
    cudaGetSymbolAddress((void**)&knew_, g_knew);
    cudaGetSymbolAddress((void**)&vnew_, g_vnew);
    cudaGetSymbolAddress((void**)&attn_, g_attn);
    cudaGetSymbolAddress((void**)&ff2_,  g_ff2);
    cudaGetSymbolAddress((void**)&vec_,  g_vec);
    cudaGetSymbolAddress((void**)&pl_,   g_pl);
    cudaGetSymbolAddress((void**)&part_, g_part);
    cudaGetSymbolAddress((void**)&cnt_,  g_cnt);

    static cudaStream_t side = nullptr;
    static cudaEvent_t evFork = nullptr, evJoin = nullptr;
    if (!side) {
        cudaStreamCreateWithFlags(&side, cudaStreamNonBlocking);
        cudaEventCreateWithFlags(&evFork, cudaEventDisableTiming);
        cudaEventCreateWithFlags(&evJoin, cudaEventDisableTiming);
    }

    // fork: KV bulk copy overlaps the entire layer loop (round-9 config)
    cudaEventRecord(evFork, 0);
    cudaStreamWaitEvent(side, evFork, 0);
    const int kvN4 = LL * KVH * SS * HDIM / 4;
    copy_kv_kernel<<<4096, 256, 0, side>>>((const float4*)K_in, (const float4*)V_in,
                                           (float4*)outK, (float4*)outV, kvN4);
    cudaEventRecord(evJoin, side);

    norm0_kernel<<<1, 256>>>(hidden, ln_in, h_, hn_);

    for (int l = 0; l < LL; l++) {
        const float* cosp = (l == 4) ? cos_f : cos_s;   // is_full only layer 4 (L=8)
        const float* sinp = (l == 4) ? sin_f : sin_s;

        const float* Wq_l   = Wq   + (size_t)l * HH * HDIM * DD;
        const float* Wk_l   = Wk   + (size_t)l * KVH * HDIM * DD;
        const float* Wv_l   = Wv   + (size_t)l * KVH * HDIM * DD;
        const float* Wo_l   = Wo   + (size_t)l * DD * HH * HDIM;
        const float* Wg_l   = Wg   + (size_t)l * FFD * DD;
        const float* Wu_l   = Wu   + (size_t)l * FFD * DD;
        const float* Wd_l   = Wd   + (size_t)l * DD * FFD;
        const float* Wplg_l = Wplg + (size_t)l * PLD * DD;
        const float* Wplp_l = Wplp + (size_t)l * DD * PLD;

        const float* Kin_l = K_in + (size_t)l * KVH * SS * HDIM;
        const float* Vin_l = V_in + (size_t)l * KVH * SS * HDIM;
        float* Kpos = outK + (size_t)l * KVH * SS * HDIM + (size_t)POSI * HDIM;
        float* Vpos = outV + (size_t)l * KVH * SS * HDIM + (size_t)POSI * HDIM;

        // attention block
        gemv_qkv_kernel<<<384, 512>>>(Wq_l, Wk_l, Wv_l, hn_, qkv_,
                                      qn + l * HDIM, kn + l * HDIM, cosp, sinp,
                                      q_, knew_, vnew_, Kpos, Vpos, cnt_ + 0);
        attn_part_kernel<<<KVH * NSPL, 256>>>(q_, Kin_l, Vin_l, knew_, vnew_, part_);
        attn_comb_kernel<<<HH, 256>>>(part_, attn_);
        gemv_kernel<DD, 2, 0><<<256, 512>>>(Wo_l, attn_, vec_, nullptr,
                                            ln_pa + l * DD, h_, ln_pre + l * DD, hn_,
                                            nullptr, nullptr, cnt_ + 1);
        // MLP block
        gemv_wgwu_kernel<<<1024, 512>>>(Wg_l, Wu_l, hn_, ff2_);
        gemv_kernel<FFD, 2, 1><<<256, 512>>>(Wd_l, ff2_, vec_, nullptr,
                                             ln_post + l * DD, h_, nullptr, nullptr,
                                             nullptr, nullptr, cnt_ + 2);
        // per-layer embedding block (uses h directly)
        gemv_kernel<DD, 1, 0><<<32, 512>>>(Wplg_l, h_, pl_, pls + l * PLD,
                                           nullptr, nullptr, nullptr, nullptr,
                                           nullptr, nullptr, nullptr);
        gemv_kernel<PLD, 3, 0><<<256, 512>>>(Wplp_l, pl_, vec_, nullptr,
                                             ln_pl + l * DD, h_,
                                             (l < LL - 1) ? (ln_in + (l + 1) * DD) : nullptr, hn_,
                                             lsc + l, (l == LL - 1) ? out : nullptr, cnt_ + 3);
    }

    cudaStreamWaitEvent(0, evJoin, 0);
}

// round 12
// speedup vs baseline: 1.0744x; 1.0341x over previous
#include <cuda_runtime.h>
#include <math.h>

#define DD   2048
#define HH   8
#define KVH  2
#define HDIM 256
#define SS   4096
#define FFD  8192
#define PLD  256
#define LL   8
#define POSI 2048
#define EPSF 1e-6f
#define NSPL 129
#define CHNK 16   // 129*16 = 2064 >= 2049 positions

// ---------------- scratch (device globals; no allocation allowed) ----------------
__device__ float g_h[DD];
__device__ float g_hn[DD];
__device__ float g_qkv[HH*HDIM + 2*KVH*HDIM];   // 3072
__device__ float g_q[HH*HDIM];
__device__ float g_knew[KVH*HDIM];
__device__ float g_vnew[KVH*HDIM];
__device__ float g_attn[HH*HDIM];
__device__ float g_ff2[2*FFD];
__device__ float g_vec[DD];
__device__ float g_pl[PLD];
__device__ float g_part[HH * NSPL * (HDIM + 2)];
__device__ unsigned g_cnt[8];          // generic self-resetting tickets

__device__ __forceinline__ void gdsync() {
#if __CUDA_ARCH__ >= 900
    cudaGridDependencySynchronize();
#endif
}
__device__ __forceinline__ void gtrig() {
#if __CUDA_ARCH__ >= 900
    cudaTriggerProgrammaticLaunchCompletion();
#endif
}

__device__ __forceinline__ float gelu_tanh(float x) {
    const float c = 0.7978845608028654f;
    return 0.5f * x * (1.0f + tanhf(c * (x + 0.044715f * x * x * x)));
}

__device__ __forceinline__ float warp_sum(float v) {
#pragma unroll
    for (int o = 16; o; o >>= 1) v += __shfl_xor_sync(0xffffffffu, v, o);
    return v;
}

__device__ __forceinline__ float warp_max(float v) {
#pragma unroll
    for (int o = 16; o; o >>= 1) v = fmaxf(v, __shfl_xor_sync(0xffffffffu, v, o));
    return v;
}

__device__ __forceinline__ float block_sum_512(float v, float* red) {
    int t = threadIdx.x;
    red[t] = v; __syncthreads();
    for (int s = 256; s > 0; s >>= 1) { if (t < s) red[t] += red[t + s]; __syncthreads(); }
    float r = red[0];
    __syncthreads();
    return r;
}

// store -> fence -> sync -> t0 atomic -> sync ; winner gets acquire fence
__device__ __forceinline__ bool last_block_ticket(unsigned* cnt, unsigned total) {
    __threadfence();
    __syncthreads();
    __shared__ unsigned isLast;
    if (threadIdx.x == 0) isLast = (atomicInc(cnt, total - 1) == total - 1);
    __syncthreads();
    if (!isLast) return false;
    __threadfence();
    return true;
}

// ---------------- KV cache bulk copy, SKIPPING row POSI of each plane ----------------
__global__ void __launch_bounds__(256) copy_kv_kernel(
        const float4* __restrict__ Ki, const float4* __restrict__ Vi,
        float4* __restrict__ Ko, float4* __restrict__ Vo, int n4) {
    int stride = gridDim.x * blockDim.x;
    for (int i = blockIdx.x * blockDim.x + threadIdx.x; i < n4; i += stride) {
        bool skip = (((i >> 6) & (SS - 1)) == POSI);   // 64 float4 per row
        if (!skip) {
            Ko[i] = Ki[i];
            Vo[i] = Vi[i];
        }
    }
}

// ---------------- h = hidden (copy) ; hn = rms(h) * w ----------------
__global__ void norm0_kernel(const float* __restrict__ hidden, const float* __restrict__ w,
                             float* __restrict__ h, float* __restrict__ hn) {
    __shared__ float red[256];
    int t = threadIdx.x;
    float hv[8]; float ss = 0.f;
#pragma unroll
    for (int j = 0; j < 8; j++) { hv[j] = hidden[t + j * 256]; ss += hv[j] * hv[j]; }
    red[t] = ss; __syncthreads();
    for (int s = 128; s > 0; s >>= 1) { if (t < s) red[t] += red[t + s]; __syncthreads(); }
    float r = rsqrtf(red[0] / (float)DD + EPSF);
#pragma unroll
    for (int j = 0; j < 8; j++) { int i = t + j * 256; h[i] = hv[j]; hn[i] = hv[j] * r * w[i]; }
}

// ---------------- fused QKV GEMV: 512 thr, warp-pair per row + last-block RMS/RoPE --------
__global__ void __launch_bounds__(512) gemv_qkv_kernel(
        const float* __restrict__ Wq, const float* __restrict__ Wk, const float* __restrict__ Wv,
        const float* __restrict__ x, float* __restrict__ y,
        const float* __restrict__ qn, const float* __restrict__ kn,
        const float* __restrict__ cosv, const float* __restrict__ sinv,
        float* __restrict__ q_out, float* __restrict__ knew, float* __restrict__ vnew,
        float* __restrict__ Kpos, float* __restrict__ Vpos,
        unsigned* __restrict__ cnt) {
    gdsync();
    __shared__ float4 sx4[DD / 4];
    const float4* x4 = (const float4*)x;
    for (int i = threadIdx.x; i < DD / 4; i += 512) sx4[i] = x4[i];
    __syncthreads();
    int warp = threadIdx.x >> 5, lane = threadIdx.x & 31;
    int half = warp & 1;
    int row = blockIdx.x * 8 + (warp >> 1);
    const float* W; int r;
    if (row < 2048)      { W = Wq; r = row; }
    else if (row < 2560) { W = Wk; r = row - 2048; }
    else                 { W = Wv; r = row - 2560; }
    const int H4 = DD / 8;   // float4 per column-half
    const float4* Wr = (const float4*)(W + (size_t)r * DD) + half * H4;
    const float4* xs = sx4 + half * H4;
    float acc = 0.f;
#pragma unroll 8
    for (int i = lane; i < H4; i += 32) {
        float4 w = Wr[i]; float4 v = xs[i];
        acc = fmaf(w.x, v.x, acc); acc = fmaf(w.y, v.y, acc);
        acc = fmaf(w.z, v.z, acc); acc = fmaf(w.w, v.w, acc);
    }
    acc = warp_sum(acc);
    __shared__ float sred[16];
    if (lane == 0) sred[warp] = acc;
    __syncthreads();
    if (threadIdx.x < 8)
        y[blockIdx.x * 8 + threadIdx.x] = sred[2 * threadIdx.x] + sred[2 * threadIdx.x + 1];
    gtrig();

    if (!last_block_ticket(cnt, gridDim.x)) return;

    for (int u = warp; u < 12; u += 16) {
        const float* src; const float* nw = nullptr; int rope = 1;
        if (u < 8)        { src = y + u * HDIM; nw = qn; }
        else if (u < 10)  { src = y + HH * HDIM + (u - 8) * HDIM; nw = kn; }
        else              { src = y + HH * HDIM + KVH * HDIM + (u - 10) * HDIM; rope = 0; }
        float v8[8]; float ss = 0.f;
#pragma unroll
        for (int j = 0; j < 8; j++) { v8[j] = src[lane * 8 + j]; ss += v8[j] * v8[j]; }
        ss = warp_sum(ss);
        float rr = rsqrtf(ss / (float)HDIM + EPSF);
#pragma unroll
        for (int j = 0; j < 8; j++) {
            int d = lane * 8 + j;
            float val = v8[j] * rr;
            if (nw) val *= nw[d];
            if (rope) {
                int p = (d < 128) ? d + 128 : d - 128;
                float pv = src[p] * rr * (nw ? nw[p] : 1.f);
                float rot = (d < 128) ? -pv : pv;
                val = val * cosv[d] + rot * sinv[d];
            }
            if (u < 8)       q_out[u * HDIM + d] = val;
            else if (u < 10) {
                int kv = u - 8;
                knew[kv * HDIM + d] = val;
                Kpos[(size_t)kv * SS * HDIM + d] = val;
            } else {
                int kv = u - 10;
                vnew[kv * HDIM + d] = val;
                Vpos[(size_t)kv * SS * HDIM + d] = val;
            }
        }
    }
}

// ---------------- attention partials: block = (kv, chunk of 16); NO ticket, NO tail --------
__global__ void __launch_bounds__(256) attn_part_kernel(
        const float* __restrict__ q,
        const float* __restrict__ Kin, const float* __restrict__ Vin,
        const float* __restrict__ knew, const float* __restrict__ vnew,
        float* __restrict__ part) {
    gdsync();
    int kv = blockIdx.x & 1;
    int chunk = blockIdx.x >> 1;
    const float* Kh = Kin + (size_t)kv * SS * HDIM;
    const float* Vh = Vin + (size_t)kv * SS * HDIM;
    const float* kn_ = knew + kv * HDIM;
    const float* vn_ = vnew + kv * HDIM;
    int t = threadIdx.x;
    int warp = t >> 5, lane = t & 31;
    int s0 = chunk * CHNK;
    int n = min(CHNK, POSI + 1 - s0);

    __shared__ float sq[4][HDIM];
    __shared__ float ssc[4][CHNK];
    __shared__ float sM[4], sL[4];
    __shared__ float spart[4][4][HDIM];
#pragma unroll
    for (int hh = 0; hh < 4; hh++) sq[hh][t] = q[(kv * 4 + hh) * HDIM + t];
    __syncthreads();

    float qreg[4][8];
#pragma unroll
    for (int hh = 0; hh < 4; hh++)
#pragma unroll
        for (int j = 0; j < 8; j++) qreg[hh][j] = sq[hh][lane * 8 + j];

    // Phase A: scores, warp per position (max 2 iterations), 4 heads per K read
    for (int idx = warp; idx < n; idx += 8) {
        int s = s0 + idx;
        const float* Kr = (s == POSI) ? kn_ : (Kh + (size_t)s * HDIM);
        float4 ka = *(const float4*)(Kr + lane * 8);
        float4 kb = *(const float4*)(Kr + lane * 8 + 4);
        float k8[8] = {ka.x, ka.y, ka.z, ka.w, kb.x, kb.y, kb.z, kb.w};
        float d0 = 0.f, d1 = 0.f, d2 = 0.f, d3 = 0.f;
#pragma unroll
        for (int j = 0; j < 8; j++) {
            d0 = fmaf(k8[j], qreg[0][j], d0);
            d1 = fmaf(k8[j], qreg[1][j], d1);
            d2 = fmaf(k8[j], qreg[2][j], d2);
            d3 = fmaf(k8[j], qreg[3][j], d3);
        }
        d0 = warp_sum(d0); d1 = warp_sum(d1);
        d2 = warp_sum(d2); d3 = warp_sum(d3);
        if (lane == 0) { ssc[0][idx] = d0; ssc[1][idx] = d1; ssc[2][idx] = d2; ssc[3][idx] = d3; }
    }
    __syncthreads();

    // Phase B: per-head softmax over <=16 positions (warp per head)
    if (warp < 4) {
        float val = (lane < n) ? ssc[warp][lane] : -1e30f;
        float M = warp_max(val);
        float e = (lane < n) ? expf(val - M) : 0.f;
        float L = warp_sum(e);
        if (lane < n) ssc[warp][lane] = e;
        if (lane == 0) { sM[warp] = M; sL[warp] = L; }
    }
    __syncthreads();

    // Phase C: V accumulation; 4 position-groups in parallel, float4 V loads
    int g = t >> 6;
    int d4 = (t & 63);
    float acc[4][4];
#pragma unroll
    for (int u = 0; u < 4; u++)
#pragma unroll
        for (int j = 0; j < 4; j++) acc[u][j] = 0.f;
    for (int idx = g; idx < n; idx += 4) {
        int s = s0 + idx;
        const float4* Vr4 = (const float4*)((s == POSI) ? vn_ : (Vh + (size_t)s * HDIM));
        float4 v = Vr4[d4];
#pragma unroll
        for (int u = 0; u < 4; u++) {
            float p = ssc[u][idx];
            acc[u][0] = fmaf(p, v.x, acc[u][0]);
            acc[u][1] = fmaf(p, v.y, acc[u][1]);
            acc[u][2] = fmaf(p, v.z, acc[u][2]);
            acc[u][3] = fmaf(p, v.w, acc[u][3]);
        }
    }
#pragma unroll
    for (int u = 0; u < 4; u++)
        *(float4*)&spart[g][u][d4 * 4] = make_float4(acc[u][0], acc[u][1], acc[u][2], acc[u][3]);
    __syncthreads();

#pragma unroll
    for (int u = 0; u < 4; u++) {
        float num = spart[0][u][t] + spart[1][u][t] + spart[2][u][t] + spart[3][u][t];
        float* pp = part + (size_t)((kv * 4 + u) * NSPL + chunk) * (HDIM + 2);
        pp[t] = num;
        if (t == 0) { pp[HDIM] = sM[u]; pp[HDIM + 1] = sL[u]; }
    }
    gtrig();
}

// ---------------- attention combine: 8 blocks (one per head), fully parallel --------
__global__ void __launch_bounds__(256) attn_comb_kernel(
        const float* __restrict__ part, float* __restrict__ out) {
    gdsync();
    int hh = blockIdx.x;
    int t = threadIdx.x;
    __shared__ float red[256];
    __shared__ float cf[NSPL];
    const float* base = part + (size_t)hh * NSPL * (HDIM + 2);

    float m = (t < NSPL) ? base[(size_t)t * (HDIM + 2) + HDIM] : -1e30f;
    red[t] = m; __syncthreads();
    for (int s = 128; s > 0; s >>= 1) { if (t < s) red[t] = fmaxf(red[t], red[t + s]); __syncthreads(); }
    float Mg = red[0];
    __syncthreads();
    float f = (t < NSPL) ? expf(m - Mg) : 0.f;
    float lv = (t < NSPL) ? base[(size_t)t * (HDIM + 2) + HDIM + 1] * f : 0.f;
    if (t < NSPL) cf[t] = f;
    red[t] = lv; __syncthreads();
    for (int s = 128; s > 0; s >>= 1) { if (t < s) red[t] += red[t + s]; __syncthreads(); }
    float Lg = red[0];
    __syncthreads();

    float num = 0.f;
#pragma unroll 8
    for (int c = 0; c < NSPL; c++)
        num = fmaf(base[(size_t)c * (HDIM + 2) + t], cf[c], num);
    out[hh * HDIM + t] = num / Lg;
}

// ---------------- dual-matrix GEMV for Wg/Wu: 512 thr, warp per row, 16 rows/block ----------
__global__ void __launch_bounds__(512) gemv_wgwu_kernel(
        const float* __restrict__ Wg, const float* __restrict__ Wu,
        const float* __restrict__ x, float* __restrict__ y) {
    gdsync();
    __shared__ float4 sx4[DD / 4];
    const float4* x4 = (const float4*)x;
    for (int i = threadIdx.x; i < DD / 4; i += 512) sx4[i] = x4[i];
    __syncthreads();
    int lane = threadIdx.x & 31;
    int row = blockIdx.x * 16 + (threadIdx.x >> 5);
    const float* W; int r;
    if (row < FFD) { W = Wg; r = row; } else { W = Wu; r = row - FFD; }
    const float4* Wr = (const float4*)(W + (size_t)r * DD);
    float acc = 0.f;
#pragma unroll 8
    for (int i = lane; i < DD / 4; i += 32) {
        float4 w = Wr[i]; float4 v = sx4[i];
        acc = fmaf(w.x, v.x, acc); acc = fmaf(w.y, v.y, acc);
        acc = fmaf(w.z, v.z, acc); acc = fmaf(w.w, v.w, acc);
    }
    acc = warp_sum(acc);
    if (lane == 0) y[row] = acc;
    gtrig();
}

// ---------------- generic 512-thr GEMV, warp-pair per row, 8 rows/block -----------------
// GATE: x has 2*COLS elements; staged x[i] = gelu(x[i]) * x[i+COLS]
// MODE 0: y = Wx ; MODE 1: y = gelu(Wx)*aux
// MODE 2: + last block: h += rms(y)*w1 ; if (w2) hn = rms(h)*w2
// MODE 3: + last block: h = (h + rms(y)*w1)*sc ; if (w2) hn = rms(h)*w2 ; if (out2) out2 = h
template<int COLS, int MODE, int GATE>
__global__ void __launch_bounds__(512) gemv_kernel(
        const float* __restrict__ W, const float* __restrict__ x, float* __restrict__ y,
        const float* __restrict__ aux,
        const float* __restrict__ w1, float* __restrict__ h,
        const float* __restrict__ w2, float* __restrict__ hn,
        const float* __restrict__ scp, float* __restrict__ out2,
        unsigned* __restrict__ cnt) {
    gdsync();
    __shared__ float4 sx4[COLS / 4];
    const float4* x4 = (const float4*)x;
    for (int i = threadIdx.x; i < COLS / 4; i += 512) {
        if (GATE) {
            float4 gg = x4[i];
            float4 uu = x4[i + COLS / 4];
            sx4[i] = make_float4(gelu_tanh(gg.x) * uu.x, gelu_tanh(gg.y) * uu.y,
                                 gelu_tanh(gg.z) * uu.z, gelu_tanh(gg.w) * uu.w);
        } else {
            sx4[i] = x4[i];
        }
    }
    __syncthreads();
    int warp = threadIdx.x >> 5, lane = threadIdx.x & 31;
    int half = warp & 1;
    int row = blockIdx.x * 8 + (warp >> 1);
    const int H4 = COLS / 8;
    const float4* Wr = (const float4*)(W + (size_t)row * COLS) + half * H4;
    const float4* xs = sx4 + half * H4;
    float acc = 0.f;
#pragma unroll 8
    for (int i = lane; i < H4; i += 32) {
        float4 w = Wr[i]; float4 v = xs[i];
        acc = fmaf(w.x, v.x, acc); acc = fmaf(w.y, v.y, acc);
        acc = fmaf(w.z, v.z, acc); acc = fmaf(w.w, v.w, acc);
    }
    acc = warp_sum(acc);
    __shared__ float sred[16];
    if (lane == 0) sred[warp] = acc;
    __syncthreads();
    if (threadIdx.x < 8) {
        float r = sred[2 * threadIdx.x] + sred[2 * threadIdx.x + 1];
        int rr = blockIdx.x * 8 + threadIdx.x;
        if (MODE == 1) r = gelu_tanh(r) * aux[rr];
        y[rr] = r;
    }
    gtrig();
    if (MODE < 2) return;

    if (!last_block_ticket(cnt, gridDim.x)) return;

    __shared__ float red[512];
    int t = threadIdx.x;
    float vv[4], hv[4]; float ss = 0.f;
#pragma unroll
    for (int j = 0; j < 4; j++) { int i = t + j * 512; vv[j] = y[i]; ss += vv[j] * vv[j]; }
    ss = block_sum_512(ss, red);
    float r1 = rsqrtf(ss / (float)DD + EPSF);
    float sc = (MODE == 3) ? scp[0] : 1.f;
    float ss2 = 0.f;
#pragma unroll
    for (int j = 0; j < 4; j++) {
        int i = t + j * 512;
        float nh = h[i] + vv[j] * r1 * w1[i];
        if (MODE == 3) nh *= sc;
        hv[j] = nh;
        h[i] = nh;
        if (MODE == 3 && out2) out2[i] = nh;
        ss2 += nh * nh;
    }
    if (w2) {
        ss2 = block_sum_512(ss2, red);
        float r2 = rsqrtf(ss2 / (float)DD + EPSF);
#pragma unroll
        for (int j = 0; j < 4; j++) { int i = t + j * 512; hn[i] = hv[j] * r2 * w2[i]; }
    }
}

// ---------------- PDL launch helper ----------------
#define PDL_LAUNCH(kfun, grid, block, ...) do {                                   \
    cudaLaunchConfig_t cfg_ = {};                                                 \
    cfg_.gridDim = dim3(grid); cfg_.blockDim = dim3(block);                       \
    cfg_.dynamicSmemBytes = 0; cfg_.stream = 0;                                   \
    cudaLaunchAttribute a_[1];                                                    \
    a_[0].id = cudaLaunchAttributeProgrammaticStreamSerialization;                \
    a_[0].val.programmaticStreamSerializationAllowed = 1;                         \
    cfg_.attrs = a_; cfg_.numAttrs = 1;                                           \
    cudaLaunchKernelEx(&cfg_, kfun, __VA_ARGS__);                                 \
} while (0)

// ==================================================================================
extern "C" void kernel_launch(void* const* d_in, const int* in_sizes, int n_in,
                              void* d_out, int out_size) {
    const float* hidden = (const float*)d_in[0];
    const float* pls    = (const float*)d_in[3];
    const float* cos_s  = (const float*)d_in[4];
    const float* sin_s  = (const float*)d_in[5];
    const float* cos_f  = (const float*)d_in[6];
    const float* sin_f  = (const float*)d_in[7];
    const float* K_in   = (const float*)d_in[8];
    const float* V_in   = (const float*)d_in[9];
    const float* Wq     = (const float*)d_in[10];
    const float* Wk     = (const float*)d_in[11];
    const float* Wv     = (const float*)d_in[12];
    const float* Wo     = (const float*)d_in[13];
    const float* qn     = (const float*)d_in[14];
    const float* kn     = (const float*)d_in[15];
    const float* ln_in  = (const float*)d_in[16];
    const float* ln_pa  = (const float*)d_in[17];
    const float* ln_pre = (const float*)d_in[18];
    const float* ln_post= (const float*)d_in[19];
    const float* ln_pl  = (const float*)d_in[20];
    const float* Wg     = (const float*)d_in[21];
    const float* Wu     = (const float*)d_in[22];
    const float* Wd     = (const float*)d_in[23];
    const float* Wplg   = (const float*)d_in[24];
    const float* Wplp   = (const float*)d_in[25];
    const float* lsc    = (const float*)d_in[26];

    float* out  = (float*)d_out;
    float* outK = out + DD;
    float* outV = outK + (size_t)LL * KVH * SS * HDIM;

    float *h_, *hn_, *qkv_, *q_, *knew_, *vnew_, *attn_, *ff2_, *vec_, *pl_, *part_;
    unsigned* cnt_;
    cudaGetSymbolAddress((void**)&h_,    g_h);
    cudaGetSymbolAddress((void**)&hn_,   g_hn);
    cudaGetSymbolAddress((void**)&qkv_,  g_qkv);
    cudaGetSymbolAddress((void**)&q_,    g_q);
    cudaGetSymbolAddress((void**)&knew_, g_knew);
    cudaGetSymbolAddress((void**)&vnew_, g_vnew);
    cudaGetSymbolAddress((void**)&attn_, g_attn);
    cudaGetSymbolAddress((void**)&ff2_,  g_ff2);
    cudaGetSymbolAddress((void**)&vec_,  g_vec);
    cudaGetSymbolAddress((void**)&pl_,   g_pl);
    cudaGetSymbolAddress((void**)&part_, g_part);
    cudaGetSymbolAddress((void**)&cnt_,  g_cnt);

    static cudaStream_t side = nullptr;
    static cudaEvent_t evFork = nullptr, evJoin = nullptr;
    if (!side) {
        cudaStreamCreateWithFlags(&side, cudaStreamNonBlocking);
        cudaEventCreateWithFlags(&evFork, cudaEventDisableTiming);
        cudaEventCreateWithFlags(&evJoin, cudaEventDisableTiming);
    }

    // fork: KV bulk copy overlaps the entire layer loop
    cudaEventRecord(evFork, 0);
    cudaStreamWaitEvent(side, evFork, 0);
    const int kvN4 = LL * KVH * SS * HDIM / 4;
    copy_kv_kernel<<<4096, 256, 0, side>>>((const float4*)K_in, (const float4*)V_in,
                                           (float4*)outK, (float4*)outV, kvN4);
    cudaEventRecord(evJoin, side);

    norm0_kernel<<<1, 256>>>(hidden, ln_in, h_, hn_);

    auto kWo   = &gemv_kernel<DD, 2, 0>;
    auto kWd   = &gemv_kernel<FFD, 2, 1>;
    auto kPlg  = &gemv_kernel<DD, 1, 0>;
    auto kPlp  = &gemv_kernel<PLD, 3, 0>;

    for (int l = 0; l < LL; l++) {
        const float* cosp = (l == 4) ? cos_f : cos_s;   // is_full only layer 4 (L=8)
        const float* sinp = (l == 4) ? sin_f : sin_s;

        const float* Wq_l   = Wq   + (size_t)l * HH * HDIM * DD;
        const float* Wk_l   = Wk   + (size_t)l * KVH * HDIM * DD;
        const float* Wv_l   = Wv   + (size_t)l * KVH * HDIM * DD;
        const float* Wo_l   = Wo   + (size_t)l * DD * HH * HDIM;
        const float* Wg_l   = Wg   + (size_t)l * FFD * DD;
        const float* Wu_l   = Wu   + (size_t)l * FFD * DD;
        const float* Wd_l   = Wd   + (size_t)l * DD * FFD;
        const float* Wplg_l = Wplg + (size_t)l * PLD * DD;
        const float* Wplp_l = Wplp + (size_t)l * DD * PLD;

        const float* Kin_l = K_in + (size_t)l * KVH * SS * HDIM;
        const float* Vin_l = V_in + (size_t)l * KVH * SS * HDIM;
        float* Kpos = outK + (size_t)l * KVH * SS * HDIM + (size_t)POSI * HDIM;
        float* Vpos = outV + (size_t)l * KVH * SS * HDIM + (size_t)POSI * HDIM;

        // attention block
        PDL_LAUNCH(gemv_qkv_kernel, 384, 512,
                   Wq_l, Wk_l, Wv_l, (const float*)hn_, (float*)qkv_,
                   qn + l * HDIM, kn + l * HDIM, cosp, sinp,
                   (float*)q_, (float*)knew_, (float*)vnew_, Kpos, Vpos, cnt_ + 0);
        PDL_LAUNCH(attn_part_kernel, KVH * NSPL, 256,
                   (const float*)q_, Kin_l, Vin_l,
                   (const float*)knew_, (const float*)vnew_, (float*)part_);
        PDL_LAUNCH(attn_comb_kernel, HH, 256, (const float*)part_, (float*)attn_);
        PDL_LAUNCH(kWo, 256, 512,
                   Wo_l, (const float*)attn_, (float*)vec_, (const float*)nullptr,
                   ln_pa + l * DD, (float*)h_, ln_pre + l * DD, (float*)hn_,
                   (const float*)nullptr, (float*)nullptr, cnt_ + 1);
        // MLP block
        PDL_LAUNCH(gemv_wgwu_kernel, 1024, 512,
                   Wg_l, Wu_l, (const float*)hn_, (float*)ff2_);
        PDL_LAUNCH(kWd, 256, 512,
                   Wd_l, (const float*)ff2_, (float*)vec_, (const float*)nullptr,
                   ln_post + l * DD, (float*)h_, (const float*)nullptr, (float*)nullptr,
                   (const float*)nullptr, (float*)nullptr, cnt_ + 2);
        // per-layer embedding block (uses h directly)
        PDL_LAUNCH(kPlg, 32, 512,
                   Wplg_l, (const float*)h_, (float*)pl_, pls + l * PLD,
                   (const float*)nullptr, (float*)nullptr, (const float*)nullptr, (float*)nullptr,
                   (const float*)nullptr, (float*)nullptr, (unsigned*)nullptr);
        PDL_LAUNCH(kPlp, 256, 512,
                   Wplp_l, (const float*)pl_, (float*)vec_, (const float*)nullptr,
                   ln_pl + l * DD, (float*)h_,
                   (l < LL - 1) ? (ln_in + (l + 1) * DD) : (const float*)nullptr, (float*)hn_,
                   lsc + l, (l == LL - 1) ? out : (float*)nullptr, cnt_ + 3);
    }

    cudaStreamWaitEvent(0, evJoin, 0);
}